// round 6
// baseline (speedup 1.0000x reference)
#include <cuda_runtime.h>
#include <math.h>

#define N_ 32
#define O_ 2048
#define I_ 4096
#define I4_ (I_/4)          // 1024
#define E_ 3
#define D_ 8
#define H_ 16
#define SELF_W 0.7f
#define OB 4                // o-rows per thread

#define MAIN_BLOCKS 592     // 148 SMs * 4 resident blocks
#define MAIN_THREADS 256
#define OG_TOTAL (O_ / OB)  // 512 o-groups

// ---------------------------------------------------------------------------
// Single fused kernel.
//  Phase 1 (warp 0 of every block, redundant & concurrent): tiny MLPs +
//           softmax -> w_s[32] in shared.
//  Phase 2 (per thread): build per-column state in REGISTERS:
//           stm  = 0.7*target_mask  (float4)
//           pm   = packed neighbor-mask bits, one uint32 per column
//           inv  = 1/(1e-8 + 0.7*tm + sum_n w[n]*nm[n])  (float4)
//           first 2048 threads also write out_b.
//  Phase 3: persistent o-group loop. Coefficients come from registers/shared
//           only: out = (tW*0.7*tm + sum_n (bit? w[n]:0)*nW) * inv.
// ---------------------------------------------------------------------------
__global__ void __launch_bounds__(MAIN_THREADS, 4)
fused_kernel(const float* __restrict__ edge_feats,
             const float* __restrict__ node_feats,
             const float* __restrict__ W1e, const float* __restrict__ b1e,
             const float* __restrict__ W2e, const float* __restrict__ b2e,
             const float* __restrict__ W1n, const float* __restrict__ b1n,
             const float* __restrict__ W2n, const float* __restrict__ b2n,
             const float4* __restrict__ tW,
             const float4* __restrict__ nW,
             const float* __restrict__ target_b,
             const float* __restrict__ neighbor_b,
             const int*   __restrict__ target_mask,
             const int*   __restrict__ neighbor_masks,
             float4* __restrict__ outW,
             float*  __restrict__ out_b)
{
    __shared__ float w_s[N_];
    const int tid = threadIdx.x;

    // ---- Phase 1: attention weights (warp 0) ----
    if (tid < N_) {
        const int n = tid;
        float logit_e = b2e[0];
        #pragma unroll
        for (int h = 0; h < H_; h++) {
            float acc = b1e[h];
            #pragma unroll
            for (int e = 0; e < E_; e++)
                acc += edge_feats[n * E_ + e] * W1e[e * H_ + h];
            logit_e += tanhf(acc) * W2e[h];
        }
        const float score = 1.f / (1.f + expf(-logit_e));

        float logit_n = b2n[0];
        #pragma unroll
        for (int h = 0; h < H_; h++) {
            float acc = b1n[h];
            #pragma unroll
            for (int d = 0; d < D_; d++)
                acc += node_feats[n * D_ + d] * W1n[d * H_ + h];
            logit_n += tanhf(acc) * W2n[h];
        }
        const float cond = 1.f / (1.f + expf(-logit_n));

        const float s = score * cond;
        float m = s;
        #pragma unroll
        for (int off = 16; off; off >>= 1)
            m = fmaxf(m, __shfl_xor_sync(0xffffffffu, m, off));
        const float ex = expf(s - m);
        float sum = ex;
        #pragma unroll
        for (int off = 16; off; off >>= 1)
            sum += __shfl_xor_sync(0xffffffffu, sum, off);
        w_s[n] = (1.f - SELF_W) * ex / sum;
    }
    __syncthreads();

    // ---- Phase 2: per-column register state ----
    const int tid0 = blockIdx.x * MAIN_THREADS + tid;   // [0, 151552)
    const int i4   = tid0 & (I4_ - 1);                  // float4 column chunk

    const int4 tmi = *(const int4*)(target_mask + i4 * 4);
    float4 stm;                                          // 0.7 * tm
    stm.x = SELF_W * (float)tmi.x;
    stm.y = SELF_W * (float)tmi.y;
    stm.z = SELF_W * (float)tmi.z;
    stm.w = SELF_W * (float)tmi.w;

    float4 norm;
    norm.x = 1e-8f + stm.x;
    norm.y = 1e-8f + stm.y;
    norm.z = 1e-8f + stm.z;
    norm.w = 1e-8f + stm.w;

    unsigned pmx = 0, pmy = 0, pmz = 0, pmw = 0;
    #pragma unroll 8
    for (int n = 0; n < N_; n++) {
        const int4 mk = *(const int4*)(neighbor_masks + n * I_ + i4 * 4);
        const float wn = w_s[n];
        norm.x += wn * (float)mk.x;
        norm.y += wn * (float)mk.y;
        norm.z += wn * (float)mk.z;
        norm.w += wn * (float)mk.w;
        pmx |= ((unsigned)mk.x) << n;
        pmy |= ((unsigned)mk.y) << n;
        pmz |= ((unsigned)mk.z) << n;
        pmw |= ((unsigned)mk.w) << n;
    }
    float4 inv;
    inv.x = 1.f / norm.x;
    inv.y = 1.f / norm.y;
    inv.z = 1.f / norm.z;
    inv.w = 1.f / norm.w;

    // ---- bias output (first 2048 threads) ----
    if (tid0 < O_) {
        float acc = SELF_W * target_b[tid0];
        #pragma unroll
        for (int n = 0; n < N_; n++)
            acc += w_s[n] * neighbor_b[n * O_ + tid0];
        out_b[tid0] = acc;
    }

    // ---- Phase 3: persistent main loop ----
    for (int og = tid0 >> 10; og < OG_TOTAL; og += MAIN_BLOCKS * MAIN_THREADS / I4_) {
        const int o0 = og * OB;

        float4 acc[OB];
        #pragma unroll
        for (int oo = 0; oo < OB; oo++) {
            const float4 t = __ldcs(&tW[(size_t)(o0 + oo) * I4_ + i4]);
            acc[oo].x = t.x * stm.x;
            acc[oo].y = t.y * stm.y;
            acc[oo].z = t.z * stm.z;
            acc[oo].w = t.w * stm.w;
        }

        #pragma unroll 4
        for (int n = 0; n < N_; n++) {
            const float wn = w_s[n];
            float4 wv;
            wv.x = ((pmx >> n) & 1u) ? wn : 0.f;
            wv.y = ((pmy >> n) & 1u) ? wn : 0.f;
            wv.z = ((pmz >> n) & 1u) ? wn : 0.f;
            wv.w = ((pmw >> n) & 1u) ? wn : 0.f;
            const size_t base = (size_t)n * (O_ * I4_);
            #pragma unroll
            for (int oo = 0; oo < OB; oo++) {
                const float4 Wv = __ldcs(&nW[base + (size_t)(o0 + oo) * I4_ + i4]);
                acc[oo].x += wv.x * Wv.x;
                acc[oo].y += wv.y * Wv.y;
                acc[oo].z += wv.z * Wv.z;
                acc[oo].w += wv.w * Wv.w;
            }
        }

        #pragma unroll
        for (int oo = 0; oo < OB; oo++) {
            float4 r;
            r.x = acc[oo].x * inv.x;
            r.y = acc[oo].y * inv.y;
            r.z = acc[oo].z * inv.z;
            r.w = acc[oo].w * inv.w;
            __stcs(&outW[(size_t)(o0 + oo) * I4_ + i4], r);
        }
    }
}

// ---------------------------------------------------------------------------
extern "C" void kernel_launch(void* const* d_in, const int* in_sizes, int n_in,
                              void* d_out, int out_size)
{
    const float* edge_feats     = (const float*)d_in[0];
    const float* node_feats     = (const float*)d_in[1];
    const float* W1e            = (const float*)d_in[2];
    const float* b1e            = (const float*)d_in[3];
    const float* W2e            = (const float*)d_in[4];
    const float* b2e            = (const float*)d_in[5];
    const float* W1n            = (const float*)d_in[6];
    const float* b1n            = (const float*)d_in[7];
    const float* W2n            = (const float*)d_in[8];
    const float* b2n            = (const float*)d_in[9];
    const float* target_W       = (const float*)d_in[10];
    const float* neighbor_W     = (const float*)d_in[11];
    const float* target_b       = (const float*)d_in[12];
    const float* neighbor_b     = (const float*)d_in[13];
    const int*   target_mask    = (const int*)d_in[14];
    const int*   neighbor_masks = (const int*)d_in[15];

    float* out   = (float*)d_out;
    float* out_b = out + (size_t)O_ * I_;

    fused_kernel<<<MAIN_BLOCKS, MAIN_THREADS>>>(
        edge_feats, node_feats,
        W1e, b1e, W2e, b2e,
        W1n, b1n, W2n, b2n,
        (const float4*)target_W, (const float4*)neighbor_W,
        target_b, neighbor_b,
        target_mask, neighbor_masks,
        (float4*)out, out_b);
}

// round 7
// speedup vs baseline: 1.0406x; 1.0406x over previous
#include <cuda_runtime.h>
#include <math.h>

#define N_ 32
#define O_ 2048
#define I_ 4096
#define I4_ (I_/4)          // 1024
#define E_ 3
#define D_ 8
#define H_ 16
#define SELF_W 0.7f
#define OB 4                // o-rows per thread

// Scratch (no allocs allowed)
__device__ float4 g_wnm4[N_ * I4_];   // w[n]*mask[n][i]/norm[i]
__device__ float4 g_a4[I4_];          // 0.7*tm[i]/norm[i]

// ---------------------------------------------------------------------------
// Fused prologue: every block's warp 0 redundantly computes the 32 attention
// weights (concurrent across blocks), then all threads compute the
// per-column coefficients + bias output.  32 blocks x 128 threads.
// ---------------------------------------------------------------------------
__global__ void __launch_bounds__(128)
prologue_kernel(const float* __restrict__ edge_feats,
                const float* __restrict__ node_feats,
                const float* __restrict__ W1e, const float* __restrict__ b1e,
                const float* __restrict__ W2e, const float* __restrict__ b2e,
                const float* __restrict__ W1n, const float* __restrict__ b1n,
                const float* __restrict__ W2n, const float* __restrict__ b2n,
                const float* __restrict__ target_b,
                const float* __restrict__ neighbor_b,
                const int*   __restrict__ target_mask,
                const int*   __restrict__ neighbor_masks,
                float* __restrict__ out_b)
{
    __shared__ float w_s[N_];
    const int tid = threadIdx.x;

    if (tid < N_) {
        const int n = tid;
        float logit_e = b2e[0];
        #pragma unroll
        for (int h = 0; h < H_; h++) {
            float acc = b1e[h];
            #pragma unroll
            for (int e = 0; e < E_; e++)
                acc += edge_feats[n * E_ + e] * W1e[e * H_ + h];
            logit_e += tanhf(acc) * W2e[h];
        }
        const float score = 1.f / (1.f + expf(-logit_e));

        float logit_n = b2n[0];
        #pragma unroll
        for (int h = 0; h < H_; h++) {
            float acc = b1n[h];
            #pragma unroll
            for (int d = 0; d < D_; d++)
                acc += node_feats[n * D_ + d] * W1n[d * H_ + h];
            logit_n += tanhf(acc) * W2n[h];
        }
        const float cond = 1.f / (1.f + expf(-logit_n));

        const float s = score * cond;
        float m = s;
        #pragma unroll
        for (int off = 16; off; off >>= 1)
            m = fmaxf(m, __shfl_xor_sync(0xffffffffu, m, off));
        const float ex = expf(s - m);
        float sum = ex;
        #pragma unroll
        for (int off = 16; off; off >>= 1)
            sum += __shfl_xor_sync(0xffffffffu, sum, off);
        w_s[n] = (1.f - SELF_W) * ex / sum;
    }
    __syncthreads();

    float* g_wnm = (float*)g_wnm4;
    float* g_a   = (float*)g_a4;

    const int i = blockIdx.x * 128 + tid;          // [0, 4096)
    {
        const float tm = (float)target_mask[i];
        float wn[N_];
        float norm = 1e-8f + SELF_W * tm;
        #pragma unroll
        for (int n = 0; n < N_; n++) {
            wn[n] = w_s[n] * (float)neighbor_masks[n * I_ + i];
            norm += wn[n];
        }
        const float inv = 1.f / norm;
        g_a[i] = SELF_W * tm * inv;
        #pragma unroll
        for (int n = 0; n < N_; n++)
            g_wnm[n * I_ + i] = wn[n] * inv;
    }

    if (i < O_) {
        float acc = SELF_W * target_b[i];
        #pragma unroll
        for (int n = 0; n < N_; n++)
            acc += w_s[n] * neighbor_b[n * O_ + i];
        out_b[i] = acc;
    }
}

// ---------------------------------------------------------------------------
// Main: out_W[o,i] = target_W[o,i]*a[i] + sum_n wnm[n,i]*neighbor_W[n,o,i]
// R2/R4 winner structure: persistent grid-stride, idx recomputed per
// iteration (short live ranges -> 64 regs -> 4 blocks/SM).
// PDL: blocks are scheduled while the prologue runs; gridDepSync gates
// the first read of g_a4 / g_wnm4.
// ---------------------------------------------------------------------------
#define MAIN_BLOCKS 592     // 148 SMs * 4 resident blocks
#define MAIN_THREADS 256

__global__ void __launch_bounds__(MAIN_THREADS)
main_kernel(const float4* __restrict__ tW,
            const float4* __restrict__ nW,
            float4* __restrict__ outW)
{
    cudaGridDependencySynchronize();

    const int total = (O_ / OB) * I4_;   // 524288 tiles
    for (int idx = blockIdx.x * MAIN_THREADS + threadIdx.x;
         idx < total;
         idx += MAIN_BLOCKS * MAIN_THREADS) {

        const int i4 = idx & (I4_ - 1);
        const int o0 = (idx >> 10) * OB;

        const float4 a = g_a4[i4];
        float4 acc[OB];
        #pragma unroll
        for (int oo = 0; oo < OB; oo++) {
            const float4 t = __ldcs(&tW[(size_t)(o0 + oo) * I4_ + i4]);
            acc[oo].x = t.x * a.x;
            acc[oo].y = t.y * a.y;
            acc[oo].z = t.z * a.z;
            acc[oo].w = t.w * a.w;
        }

        #pragma unroll 4
        for (int n = 0; n < N_; n++) {
            const float4 wv = g_wnm4[n * I4_ + i4];          // L1/L2-resident
            const size_t base = (size_t)n * (O_ * I4_);
            #pragma unroll
            for (int oo = 0; oo < OB; oo++) {
                const float4 Wv = __ldcs(&nW[base + (size_t)(o0 + oo) * I4_ + i4]);
                acc[oo].x += wv.x * Wv.x;
                acc[oo].y += wv.y * Wv.y;
                acc[oo].z += wv.z * Wv.z;
                acc[oo].w += wv.w * Wv.w;
            }
        }

        #pragma unroll
        for (int oo = 0; oo < OB; oo++)
            __stcs(&outW[(size_t)(o0 + oo) * I4_ + i4], acc[oo]);
    }
}

// ---------------------------------------------------------------------------
extern "C" void kernel_launch(void* const* d_in, const int* in_sizes, int n_in,
                              void* d_out, int out_size)
{
    const float* edge_feats     = (const float*)d_in[0];
    const float* node_feats     = (const float*)d_in[1];
    const float* W1e            = (const float*)d_in[2];
    const float* b1e            = (const float*)d_in[3];
    const float* W2e            = (const float*)d_in[4];
    const float* b2e            = (const float*)d_in[5];
    const float* W1n            = (const float*)d_in[6];
    const float* b1n            = (const float*)d_in[7];
    const float* W2n            = (const float*)d_in[8];
    const float* b2n            = (const float*)d_in[9];
    const float* target_W       = (const float*)d_in[10];
    const float* neighbor_W     = (const float*)d_in[11];
    const float* target_b       = (const float*)d_in[12];
    const float* neighbor_b     = (const float*)d_in[13];
    const int*   target_mask    = (const int*)d_in[14];
    const int*   neighbor_masks = (const int*)d_in[15];

    float* out   = (float*)d_out;
    float* out_b = out + (size_t)O_ * I_;

    prologue_kernel<<<I_ / 128, 128>>>(edge_feats, node_feats,
                                       W1e, b1e, W2e, b2e,
                                       W1n, b1n, W2n, b2n,
                                       target_b, neighbor_b,
                                       target_mask, neighbor_masks,
                                       out_b);

    // Programmatic dependent launch of the main kernel: scheduled while the
    // prologue runs; cudaGridDependencySynchronize() inside gates the reads.
    {
        cudaLaunchConfig_t cfg = {};
        cfg.gridDim  = dim3(MAIN_BLOCKS, 1, 1);
        cfg.blockDim = dim3(MAIN_THREADS, 1, 1);
        cfg.dynamicSmemBytes = 0;
        cfg.stream = 0;   // same (capture) stream as the prologue launch

        cudaLaunchAttribute attrs[1];
        attrs[0].id = cudaLaunchAttributeProgrammaticStreamSerialization;
        attrs[0].val.programmaticStreamSerializationAllowed = 1;
        cfg.attrs = attrs;
        cfg.numAttrs = 1;

        cudaLaunchKernelEx(&cfg, main_kernel,
                           (const float4*)target_W,
                           (const float4*)neighbor_W,
                           (float4*)out);
    }
}